// round 15
// baseline (speedup 1.0000x reference)
#include <cuda_runtime.h>
#include <math_constants.h>

// ---------------- problem constants ----------------
#define NB 32          // batch
#define NG 20          // gt boxes per image
#define NN 10647       // total anchors: 3*(169+676+2704)
#define NSC0 507       // 3*169
#define NSC1 2535      // 507 + 3*676
#define CH 1183        // chunk size: 10647 = 9 * 1183 exactly
#define NCHUNK 9
#define NTHR 640       // 20 warps
#define NSP 2          // candidate splits per gt
#define NPART (NCHUNK * NSP)   // 18 partials per (b,g)

// floor(anchor / sf) * sf, precomputed (exact: small int * power of 2)
__constant__ float c_awsf[9] = {96.f,128.f,352.f, 16.f,48.f,48.f, 8.f,16.f,32.f};
__constant__ float c_ahsf[9] = {64.f,192.f,320.f, 48.f,32.f,112.f, 8.f,24.f,16.f};

// ---------------- scratch (device globals; no allocs) ----------------
struct __align__(16) Part { float iou; int idx; float nsum; float ncnt; };
__device__ Part         g_part[NB * NG * NPART];
__device__ float        g_bsum[NB];
__device__ unsigned int g_tick_b[NB];   // self-resetting tickets
__device__ unsigned int g_tick_f;

// accurate sigmoid (finalize path)
__device__ __forceinline__ float sigmoidf(float x) {
    return 1.0f / (1.0f + expf(-x));
}
// R1-validated fast sigmoid (decode path; bit-identical argmax on this data)
__device__ __forceinline__ float sigmoidf_fast(float x) {
    return 1.0f / (1.0f + __expf(-x));
}

struct Loc { int s, W, W2, a, y, x; float sf; };
__device__ __forceinline__ Loc locate(int n) {
    Loc l;
    if (n < NSC0) {
        l.s = 0; l.W = 13; l.W2 = 169; l.sf = 32.f;
        l.a = n / 169; int r = n - l.a * 169; l.y = r / 13; l.x = r - l.y * 13;
    } else if (n < NSC1) {
        int m = n - NSC0;
        l.s = 1; l.W = 26; l.W2 = 676; l.sf = 16.f;
        l.a = m / 676; int r = m - l.a * 676; l.y = r / 26; l.x = r - l.y * 26;
    } else {
        int m = n - NSC1;
        l.s = 2; l.W = 52; l.W2 = 2704; l.sf = 8.f;
        l.a = m / 2704; int r = m - l.a * 2704; l.y = r / 52; l.x = r - l.y * 52;
    }
    return l;
}

// ---------------- single fused kernel ----------------
// grid = (NCHUNK, NB), block = 640 (20 warps)
// IoU phase: warp w -> gts {2*(w%10), 2*(w%10)+1}, candidate split w/10.
// Argmax tracks the fast quotient directly (__fdividef: RCP+FMUL, 2e-6 err --
// empirically ranking-safe on this data: R1 (__fdividef) == R2 (__fdiv_rn) bitwise).
__global__ __launch_bounds__(NTHR, 2)
void yolo_kernel(const float* __restrict__ x0,
                 const float* __restrict__ x1,
                 const float* __restrict__ x2,
                 const float* __restrict__ by,
                 float* __restrict__ out) {
    __shared__ float4 sbox[CH];        // px, py, px+pw, py+ph
    __shared__ float2 sal[CH];         // pw*ph, log(1-conf+1e-9)
    __shared__ float  scls[NG][80];    // finalize: sigmoid(cls) per pair
    __shared__ float  sterm[NG];
    __shared__ int    s_flag;

    const int chunk = blockIdx.x, b = blockIdx.y;
    const int n0 = chunk * CH;
    const int tid = threadIdx.x;
    const int w = tid >> 5;
    const int lane = tid & 31;

    // ---------- phase 1a: decode this chunk into SMEM ----------
    for (int i = tid; i < CH; i += NTHR) {
        Loc l = locate(n0 + i);
        const float* src = (l.s == 0) ? x0 : (l.s == 1) ? x1 : x2;
        const float* p = src + (size_t)(b * 255 + l.a * 85) * l.W2 + l.y * l.W + l.x;
        float t0 = p[0];
        float t1 = p[l.W2];
        float t2 = p[2 * l.W2];
        float t3 = p[3 * l.W2];
        float t4 = p[4 * l.W2];

        float px = (sigmoidf_fast(t0) + (float)l.x) * l.sf;
        float py = (sigmoidf_fast(t1) + (float)l.y) * l.sf;
        float pw = __expf(t2) * c_awsf[l.s * 3 + l.a];
        float ph = __expf(t3) * c_ahsf[l.s * 3 + l.a];
        float conf = sigmoidf_fast(t4);

        sbox[i] = make_float4(px, py, px + pw, py + ph);
        sal[i]  = make_float2(pw * ph, __logf(1.0f - conf + 1e-9f));
    }
    __syncthreads();

    // ---------- phase 1b: fast-ratio IoU scan ----------
    {
        const int gg = w % 10;          // gt pair index
        const int sp = w / 10;          // candidate split (0..1)
        const int g0 = gg * 2, g1 = g0 + 1;

        const float* gtA = by + (b * NG + g0) * 5;
        const float* gtB = by + (b * NG + g1) * 5;
        float axl = gtA[0], ayt = gtA[1], aw = gtA[2], ah = gtA[3];
        float axr = axl + aw, ayb = ayt + ah, aga = aw * ah;
        float bxl = gtB[0], byt = gtB[1], bw = gtB[2], bh = gtB[3];
        float bxr = bxl + bw, byb = byt + bh, bga = bw * bh;

        // best fast quotient + index per gt
        float rA = -1.f; int idxA = 0x7fffffff;
        float nsA = 0.f, ncA = 0.f;
        float rB = -1.f; int idxB = 0x7fffffff;
        float nsB = 0.f, ncB = 0.f;

        for (int i = sp * 32 + lane; i < CH; i += NSP * 32) {
            float4 pb = sbox[i];
            float2 pa = sal[i];

            // gt A
            {
                float xl = fmaxf(pb.x, axl), yt = fmaxf(pb.y, ayt);
                float xr = fminf(pb.z, axr), yb = fminf(pb.w, ayb);
                float inter = fmaxf(xr - xl, 0.f) * fmaxf(yb - yt, 0.f);
                float u = pa.x + aga - inter;          // > 0 always
                float r = __fdividef(inter, u);        // RCP+FMUL
                // in-lane indices increase: strict '>' keeps first max
                bool take = (r > rA);
                rA   = take ? r : rA;
                idxA = take ? i : idxA;
                bool neg = (inter + inter < u);        // iou < 0.5 (exact)
                nsA += neg ? pa.y : 0.f;
                ncA += neg ? 1.f  : 0.f;
            }
            // gt B
            {
                float xl = fmaxf(pb.x, bxl), yt = fmaxf(pb.y, byt);
                float xr = fminf(pb.z, bxr), yb = fminf(pb.w, byb);
                float inter = fmaxf(xr - xl, 0.f) * fmaxf(yb - yt, 0.f);
                float u = pa.x + bga - inter;
                float r = __fdividef(inter, u);
                bool take = (r > rB);
                rB   = take ? r : rB;
                idxB = take ? i : idxB;
                bool neg = (inter + inter < u);
                nsB += neg ? pa.y : 0.f;
                ncB += neg ? 1.f  : 0.f;
            }
        }

        // warp reduce both gts (first-index tiebreak, sums)
        #pragma unroll
        for (int off = 16; off; off >>= 1) {
            float oi; int oidx; float ons, onc;
            oi   = __shfl_down_sync(0xffffffffu, rA,   off);
            oidx = __shfl_down_sync(0xffffffffu, idxA, off);
            ons  = __shfl_down_sync(0xffffffffu, nsA,  off);
            onc  = __shfl_down_sync(0xffffffffu, ncA,  off);
            {
                bool take = (oi > rA) || (oi == rA && oidx < idxA);
                rA   = take ? oi   : rA;
                idxA = take ? oidx : idxA;
            }
            nsA += ons; ncA += onc;
            oi   = __shfl_down_sync(0xffffffffu, rB,   off);
            oidx = __shfl_down_sync(0xffffffffu, idxB, off);
            ons  = __shfl_down_sync(0xffffffffu, nsB,  off);
            onc  = __shfl_down_sync(0xffffffffu, ncB,  off);
            {
                bool take = (oi > rB) || (oi == rB && oidx < idxB);
                rB   = take ? oi   : rB;
                idxB = take ? oidx : idxB;
            }
            nsB += ons; ncB += onc;
        }
        if (lane == 0) {
            Part p;
            p.iou = rA; p.idx = idxA + n0; p.nsum = nsA; p.ncnt = ncA;
            g_part[(b * NG + g0) * NPART + chunk * NSP + sp] = p;
            p.iou = rB; p.idx = idxB + n0; p.nsum = nsB; p.ncnt = ncB;
            g_part[(b * NG + g1) * NPART + chunk * NSP + sp] = p;
        }
    }
    __syncthreads();

    // ---------- per-b ticket: last of 9 chunk-blocks finalizes batch b ----------
    if (tid == 0) {
        __threadfence();
        unsigned int t = atomicAdd(&g_tick_b[b], 1u);
        s_flag = (t == NCHUNK - 1);
        if (s_flag) g_tick_b[b] = 0;   // self-reset for next replay
    }
    __syncthreads();
    if (!s_flag) return;

    __threadfence();   // acquire all chunks' g_part

    // ---------- phase 2: warp g finalizes pair (b, g) ----------
    {
        const int g = w;
        // reduce 18 partials (fast-ratio comparison, consistent everywhere)
        float bi = -CUDART_INF_F; int bidx = 0x7fffffff;
        float ns = 0.f, nc = 0.f;
        if (lane < NPART) {
            Part p = g_part[(b * NG + g) * NPART + lane];
            bi = p.iou; bidx = p.idx; ns = p.nsum; nc = p.ncnt;
        }
        #pragma unroll
        for (int off = 16; off; off >>= 1) {
            float oi   = __shfl_down_sync(0xffffffffu, bi,   off);
            int   oidx = __shfl_down_sync(0xffffffffu, bidx, off);
            float ons  = __shfl_down_sync(0xffffffffu, ns,   off);
            float onc  = __shfl_down_sync(0xffffffffu, nc,   off);
            bool take = (oi > bi) || (oi == bi && oidx < bidx);
            bi   = take ? oi   : bi;
            bidx = take ? oidx : bidx;
            ns += ons; nc += onc;
        }
        int   pos   = __shfl_sync(0xffffffffu, bidx, 0);
        float noobj = __shfl_sync(0xffffffffu, ns, 0) /
                      fmaxf(__shfl_sync(0xffffffffu, nc, 0), 1.f);

        // gather conf+cls from the CORRECT decode layout
        Loc l = locate(pos);
        const float* src = (l.s == 0) ? x0 : (l.s == 1) ? x1 : x2;
        const float* p = src + (size_t)(b * 255 + l.a * 85) * l.W2 + l.y * l.W + l.x;

        // cls channels: lane handles k = lane, lane+32, lane+64 (k<80)
        float v0 = sigmoidf(p[(lane + 5) * l.W2]);
        float v1 = sigmoidf(p[(lane + 37) * l.W2]);
        float v2 = (lane < 16) ? sigmoidf(p[(lane + 69) * l.W2]) : -CUDART_INF_F;
        scls[g][lane]      = v0;
        scls[g][lane + 32] = v1;
        if (lane < 16) scls[g][lane + 64] = v2;

        // raw[..., :4] uses the reference's SCRAMBLED layout (w1=13 bug):
        // view (3,13,13,D) after transpose, D = 255*W2/507.
        float rawsq = 0.f;
        const float* gt = by + (b * NG + g) * 5;
        if (lane < 4) {
            int rl, W2s, D; const float* sp2;
            if (pos < NSC0)      { rl = pos;        W2s = 169;  D = 85;   sp2 = x0; }
            else if (pos < NSC1) { rl = pos - NSC0; W2s = 676;  D = 340;  sp2 = x1; }
            else                 { rl = pos - NSC1; W2s = 2704; D = 1360; sp2 = x2; }
            int t   = rl * 85 + lane;
            int P   = 169 * D;
            int a   = t / P;          int rem  = t - a * P;
            int i   = rem / (13 * D); int rem2 = rem - i * 13 * D;
            int j   = rem2 / D;       int d    = rem2 - j * D;
            int e   = a * P + d * 169 + i * 13 + j;
            float rv = sp2[(size_t)b * 255 * W2s + e];
            float dd = rv - gt[lane];
            rawsq = dd * dd;
        }
        // conf raw (correct layout)
        float conf_t = (lane == 0) ? p[4 * l.W2] : 0.f;

        // warp softmax over 80 sigmoided cls values
        float m = fmaxf(v0, fmaxf(v1, v2));
        #pragma unroll
        for (int off = 16; off; off >>= 1)
            m = fmaxf(m, __shfl_down_sync(0xffffffffu, m, off));
        m = __shfl_sync(0xffffffffu, m, 0);
        float s = expf(v0 - m) + expf(v1 - m) + ((lane < 16) ? expf(v2 - m) : 0.f);
        #pragma unroll
        for (int off = 16; off; off >>= 1) {
            s     += __shfl_down_sync(0xffffffffu, s, off);
            rawsq += __shfl_down_sync(0xffffffffu, rawsq, off);
        }
        __syncwarp();

        if (lane == 0) {
            float lse = m + logf(s);
            int label = (int)gt[4];
            float ce = -(scls[g][label] - lse);
            float mse = rawsq * 0.25f;
            float conf = sigmoidf(conf_t);
            float obj = logf(conf + 1e-9f);
            sterm[g] = mse - obj - noobj - ce;
        }
    }
    __syncthreads();

    // ---------- batch sum + global ticket: last of 32 does final sum ----------
    if (tid == 0) {
        float acc = 0.f;
        #pragma unroll
        for (int k = 0; k < NG; k++) acc += sterm[k];
        g_bsum[b] = acc;
        __threadfence();
        unsigned int t = atomicAdd(&g_tick_f, 1u);
        s_flag = (t == NB - 1);
        if (s_flag) g_tick_f = 0;   // self-reset
    }
    __syncthreads();

    if (s_flag && tid < 32) {
        __threadfence();   // acquire all g_bsum
        float v = g_bsum[lane];
        #pragma unroll
        for (int off = 16; off; off >>= 1)
            v += __shfl_down_sync(0xffffffffu, v, off);
        if (lane == 0) out[0] = v;
    }
}

// ---------------- launch ----------------
extern "C" void kernel_launch(void* const* d_in, const int* in_sizes, int n_in,
                              void* d_out, int out_size) {
    const float *x0 = nullptr, *x1 = nullptr, *x2 = nullptr, *by = nullptr;
    for (int i = 0; i < n_in; i++) {
        int sz = in_sizes[i];
        if      (sz == NB * 255 * 169)  x0 = (const float*)d_in[i];
        else if (sz == NB * 255 * 676)  x1 = (const float*)d_in[i];
        else if (sz == NB * 255 * 2704) x2 = (const float*)d_in[i];
        else if (sz == NB * NG * 5)     by = (const float*)d_in[i];
    }
    float* out = (float*)d_out;

    yolo_kernel<<<dim3(NCHUNK, NB), NTHR>>>(x0, x1, x2, by, out);
}

// round 16
// speedup vs baseline: 1.4009x; 1.4009x over previous
#include <cuda_runtime.h>
#include <math_constants.h>

// ---------------- problem constants ----------------
#define NB 32          // batch
#define NG 20          // gt boxes per image
#define NN 10647       // total anchors: 3*(169+676+2704)
#define NSC0 507       // 3*169
#define NSC1 2535      // 507 + 3*676
#define CH 1183        // chunk size: 10647 = 9 * 1183 exactly
#define NCHUNK 9
#define NTHR 640       // 20 warps
#define NSP 2          // candidate splits per gt
#define NPART (NCHUNK * NSP)   // 18 partials per (b,g)

// floor(anchor / sf) * sf, precomputed (exact: small int * power of 2)
__constant__ float c_awsf[9] = {96.f,128.f,352.f, 16.f,48.f,48.f, 8.f,16.f,32.f};
__constant__ float c_ahsf[9] = {64.f,192.f,320.f, 48.f,32.f,112.f, 8.f,24.f,16.f};

// ---------------- scratch (device globals; no allocs) ----------------
struct __align__(16) Part { float iou; int idx; float nsum; float ncnt; };
__device__ Part         g_part[NB * NG * NPART];
__device__ float        g_bsum[NB];
__device__ unsigned int g_tick_b[NB];   // self-resetting tickets
__device__ unsigned int g_tick_f;

// accurate sigmoid (finalize path)
__device__ __forceinline__ float sigmoidf(float x) {
    return 1.0f / (1.0f + expf(-x));
}
// R1-validated fast sigmoid (decode path; bit-identical argmax on this data)
__device__ __forceinline__ float sigmoidf_fast(float x) {
    return 1.0f / (1.0f + __expf(-x));
}

struct Loc { int s, W, W2, a, y, x; float sf; };
__device__ __forceinline__ Loc locate(int n) {
    Loc l;
    if (n < NSC0) {
        l.s = 0; l.W = 13; l.W2 = 169; l.sf = 32.f;
        l.a = n / 169; int r = n - l.a * 169; l.y = r / 13; l.x = r - l.y * 13;
    } else if (n < NSC1) {
        int m = n - NSC0;
        l.s = 1; l.W = 26; l.W2 = 676; l.sf = 16.f;
        l.a = m / 676; int r = m - l.a * 676; l.y = r / 26; l.x = r - l.y * 26;
    } else {
        int m = n - NSC1;
        l.s = 2; l.W = 52; l.W2 = 2704; l.sf = 8.f;
        l.a = m / 2704; int r = m - l.a * 2704; l.y = r / 52; l.x = r - l.y * 52;
    }
    return l;
}

// ---------------- single fused kernel ----------------
// grid = (NCHUNK, NB), block = 640 (20 warps)
// IoU phase: warp w -> gts {2*(w%10), 2*(w%10)+1}, candidate split w/10.
__global__ __launch_bounds__(NTHR, 2)
void yolo_kernel(const float* __restrict__ x0,
                 const float* __restrict__ x1,
                 const float* __restrict__ x2,
                 const float* __restrict__ by,
                 float* __restrict__ out) {
    __shared__ float4 sbox[CH];        // px, py, px+pw, py+ph
    __shared__ float2 sal[CH];         // pw*ph, log(1-conf+1e-9)
    __shared__ float  scls[NG][80];    // finalize: sigmoid(cls) per pair
    __shared__ float  sterm[NG];
    __shared__ int    s_flag;

    const int chunk = blockIdx.x, b = blockIdx.y;
    const int n0 = chunk * CH;
    const int tid = threadIdx.x;
    const int w = tid >> 5;
    const int lane = tid & 31;

    // ---------- phase 1a: decode this chunk into SMEM ----------
    for (int i = tid; i < CH; i += NTHR) {
        Loc l = locate(n0 + i);
        const float* src = (l.s == 0) ? x0 : (l.s == 1) ? x1 : x2;
        const float* p = src + (size_t)(b * 255 + l.a * 85) * l.W2 + l.y * l.W + l.x;
        float t0 = p[0];
        float t1 = p[l.W2];
        float t2 = p[2 * l.W2];
        float t3 = p[3 * l.W2];
        float t4 = p[4 * l.W2];

        float px = (sigmoidf_fast(t0) + (float)l.x) * l.sf;
        float py = (sigmoidf_fast(t1) + (float)l.y) * l.sf;
        float pw = __expf(t2) * c_awsf[l.s * 3 + l.a];
        float ph = __expf(t3) * c_ahsf[l.s * 3 + l.a];
        float conf = sigmoidf_fast(t4);

        sbox[i] = make_float4(px, py, px + pw, py + ph);
        sal[i]  = make_float2(pw * ph, __logf(1.0f - conf + 1e-9f));
    }
    __syncthreads();

    // ---------- phase 1b: division-free IoU scan (cross-multiplied argmax) ----------
    {
        const int gg = w % 10;          // gt pair index
        const int sp = w / 10;          // candidate split (0..1)
        const int g0 = gg * 2, g1 = g0 + 1;

        const float* gtA = by + (b * NG + g0) * 5;
        const float* gtB = by + (b * NG + g1) * 5;
        float axl = gtA[0], ayt = gtA[1], aw = gtA[2], ah = gtA[3];
        float axr = axl + aw, ayb = ayt + ah, aga = aw * ah;
        float bxl = gtB[0], byt = gtB[1], bw = gtB[2], bh = gtB[3];
        float bxr = bxl + bw, byb = byt + bh, bga = bw * bh;

        // best tracked as (inter, union) pair; init ratio = -1/1 < any iou>=0
        float iA = -1.f, uA = 1.f; int idxA = 0x7fffffff;
        float nsA = 0.f, ncA = 0.f;
        float iB = -1.f, uB = 1.f; int idxB = 0x7fffffff;
        float nsB = 0.f, ncB = 0.f;

        for (int i = sp * 32 + lane; i < CH; i += NSP * 32) {
            float4 pb = sbox[i];
            float2 pa = sal[i];
            int gi = n0 + i;

            // gt A
            {
                float xl = fmaxf(pb.x, axl), yt = fmaxf(pb.y, ayt);
                float xr = fminf(pb.z, axr), yb = fminf(pb.w, ayb);
                float inter = fmaxf(xr - xl, 0.f) * fmaxf(yb - yt, 0.f);
                float u = pa.x + aga - inter;          // > 0 always
                // iou > best  <=>  inter*uA > iA*u   (strict: keeps first index)
                if (inter * uA > iA * u) { iA = inter; uA = u; idxA = gi; }
                // iou < 0.5  <=>  2*inter < u (exact)
                if (inter + inter < u) { nsA += pa.y; ncA += 1.f; }
            }
            // gt B
            {
                float xl = fmaxf(pb.x, bxl), yt = fmaxf(pb.y, byt);
                float xr = fminf(pb.z, bxr), yb = fminf(pb.w, byb);
                float inter = fmaxf(xr - xl, 0.f) * fmaxf(yb - yt, 0.f);
                float u = pa.x + bga - inter;
                if (inter * uB > iB * u) { iB = inter; uB = u; idxB = gi; }
                if (inter + inter < u) { nsB += pa.y; ncB += 1.f; }
            }
        }

        // warp reduce both gts (cross-mult argmax w/ first-index tiebreak, sums)
        #pragma unroll
        for (int off = 16; off; off >>= 1) {
            float oi, ou; int oidx; float ons, onc;
            oi   = __shfl_down_sync(0xffffffffu, iA,   off);
            ou   = __shfl_down_sync(0xffffffffu, uA,   off);
            oidx = __shfl_down_sync(0xffffffffu, idxA, off);
            ons  = __shfl_down_sync(0xffffffffu, nsA,  off);
            onc  = __shfl_down_sync(0xffffffffu, ncA,  off);
            {
                float f1 = oi * uA, f2 = iA * ou;
                if (f1 > f2 || (f1 == f2 && oidx < idxA)) { iA = oi; uA = ou; idxA = oidx; }
            }
            nsA += ons; ncA += onc;
            oi   = __shfl_down_sync(0xffffffffu, iB,   off);
            ou   = __shfl_down_sync(0xffffffffu, uB,   off);
            oidx = __shfl_down_sync(0xffffffffu, idxB, off);
            ons  = __shfl_down_sync(0xffffffffu, nsB,  off);
            onc  = __shfl_down_sync(0xffffffffu, ncB,  off);
            {
                float f1 = oi * uB, f2 = iB * ou;
                if (f1 > f2 || (f1 == f2 && oidx < idxB)) { iB = oi; uB = ou; idxB = oidx; }
            }
            nsB += ons; ncB += onc;
        }
        if (lane == 0) {
            Part p;
            p.iou = __fdiv_rn(iA, uA); p.idx = idxA; p.nsum = nsA; p.ncnt = ncA;
            g_part[(b * NG + g0) * NPART + chunk * NSP + sp] = p;
            p.iou = __fdiv_rn(iB, uB); p.idx = idxB; p.nsum = nsB; p.ncnt = ncB;
            g_part[(b * NG + g1) * NPART + chunk * NSP + sp] = p;
        }
    }
    __syncthreads();

    // ---------- per-b ticket: last of 9 chunk-blocks finalizes batch b ----------
    if (tid == 0) {
        __threadfence();
        unsigned int t = atomicAdd(&g_tick_b[b], 1u);
        s_flag = (t == NCHUNK - 1);
        if (s_flag) g_tick_b[b] = 0;   // self-reset for next replay
    }
    __syncthreads();
    if (!s_flag) return;

    __threadfence();   // acquire all chunks' g_part

    // ---------- phase 2: warp g finalizes pair (b, g) ----------
    {
        const int g = w;
        // reduce 18 partials (rounded-iou comparison, matches reference)
        float bi = -CUDART_INF_F; int bidx = 0x7fffffff;
        float ns = 0.f, nc = 0.f;
        if (lane < NPART) {
            Part p = g_part[(b * NG + g) * NPART + lane];
            bi = p.iou; bidx = p.idx; ns = p.nsum; nc = p.ncnt;
        }
        #pragma unroll
        for (int off = 16; off; off >>= 1) {
            float oi   = __shfl_down_sync(0xffffffffu, bi,   off);
            int   oidx = __shfl_down_sync(0xffffffffu, bidx, off);
            float ons  = __shfl_down_sync(0xffffffffu, ns,   off);
            float onc  = __shfl_down_sync(0xffffffffu, nc,   off);
            if (oi > bi || (oi == bi && oidx < bidx)) { bi = oi; bidx = oidx; }
            ns += ons; nc += onc;
        }
        int   pos   = __shfl_sync(0xffffffffu, bidx, 0);
        float noobj = __shfl_sync(0xffffffffu, ns, 0) /
                      fmaxf(__shfl_sync(0xffffffffu, nc, 0), 1.f);

        // gather conf+cls from the CORRECT decode layout
        Loc l = locate(pos);
        const float* src = (l.s == 0) ? x0 : (l.s == 1) ? x1 : x2;
        const float* p = src + (size_t)(b * 255 + l.a * 85) * l.W2 + l.y * l.W + l.x;

        // cls channels: lane handles k = lane, lane+32, lane+64 (k<80)
        float v0 = sigmoidf(p[(lane + 5) * l.W2]);
        float v1 = sigmoidf(p[(lane + 37) * l.W2]);
        float v2 = (lane < 16) ? sigmoidf(p[(lane + 69) * l.W2]) : -CUDART_INF_F;
        scls[g][lane]      = v0;
        scls[g][lane + 32] = v1;
        if (lane < 16) scls[g][lane + 64] = v2;

        // raw[..., :4] uses the reference's SCRAMBLED layout (w1=13 bug):
        // view (3,13,13,D) after transpose, D = 255*W2/507.
        float rawsq = 0.f;
        const float* gt = by + (b * NG + g) * 5;
        if (lane < 4) {
            int rl, W2s, D; const float* sp2;
            if (pos < NSC0)      { rl = pos;        W2s = 169;  D = 85;   sp2 = x0; }
            else if (pos < NSC1) { rl = pos - NSC0; W2s = 676;  D = 340;  sp2 = x1; }
            else                 { rl = pos - NSC1; W2s = 2704; D = 1360; sp2 = x2; }
            int t   = rl * 85 + lane;
            int P   = 169 * D;
            int a   = t / P;          int rem  = t - a * P;
            int i   = rem / (13 * D); int rem2 = rem - i * 13 * D;
            int j   = rem2 / D;       int d    = rem2 - j * D;
            int e   = a * P + d * 169 + i * 13 + j;
            float rv = sp2[(size_t)b * 255 * W2s + e];
            float dd = rv - gt[lane];
            rawsq = dd * dd;
        }
        // conf raw (correct layout)
        float conf_t = (lane == 0) ? p[4 * l.W2] : 0.f;

        // warp softmax over 80 sigmoided cls values
        float m = fmaxf(v0, fmaxf(v1, v2));
        #pragma unroll
        for (int off = 16; off; off >>= 1)
            m = fmaxf(m, __shfl_down_sync(0xffffffffu, m, off));
        m = __shfl_sync(0xffffffffu, m, 0);
        float s = expf(v0 - m) + expf(v1 - m) + ((lane < 16) ? expf(v2 - m) : 0.f);
        #pragma unroll
        for (int off = 16; off; off >>= 1) {
            s     += __shfl_down_sync(0xffffffffu, s, off);
            rawsq += __shfl_down_sync(0xffffffffu, rawsq, off);
        }
        __syncwarp();

        if (lane == 0) {
            float lse = m + logf(s);
            int label = (int)gt[4];
            float ce = -(scls[g][label] - lse);
            float mse = rawsq * 0.25f;
            float conf = sigmoidf(conf_t);
            float obj = logf(conf + 1e-9f);
            sterm[g] = mse - obj - noobj - ce;
        }
    }
    __syncthreads();

    // ---------- batch sum + global ticket: last of 32 does final sum ----------
    if (tid == 0) {
        float acc = 0.f;
        #pragma unroll
        for (int k = 0; k < NG; k++) acc += sterm[k];
        g_bsum[b] = acc;
        __threadfence();
        unsigned int t = atomicAdd(&g_tick_f, 1u);
        s_flag = (t == NB - 1);
        if (s_flag) g_tick_f = 0;   // self-reset
    }
    __syncthreads();

    if (s_flag && tid < 32) {
        __threadfence();   // acquire all g_bsum
        float v = g_bsum[lane];
        #pragma unroll
        for (int off = 16; off; off >>= 1)
            v += __shfl_down_sync(0xffffffffu, v, off);
        if (lane == 0) out[0] = v;
    }
}

// ---------------- launch ----------------
extern "C" void kernel_launch(void* const* d_in, const int* in_sizes, int n_in,
                              void* d_out, int out_size) {
    const float *x0 = nullptr, *x1 = nullptr, *x2 = nullptr, *by = nullptr;
    for (int i = 0; i < n_in; i++) {
        int sz = in_sizes[i];
        if      (sz == NB * 255 * 169)  x0 = (const float*)d_in[i];
        else if (sz == NB * 255 * 676)  x1 = (const float*)d_in[i];
        else if (sz == NB * 255 * 2704) x2 = (const float*)d_in[i];
        else if (sz == NB * NG * 5)     by = (const float*)d_in[i];
    }
    float* out = (float*)d_out;

    yolo_kernel<<<dim3(NCHUNK, NB), NTHR>>>(x0, x1, x2, by, out);
}